// round 9
// baseline (speedup 1.0000x reference)
#include <cuda_runtime.h>
#include <cuda_fp16.h>
#include <stdint.h>
#include <math.h>

#define B_    128
#define N_    196
#define ENC_  2048
#define DEC_  512
#define ATT_  512
#define M_    (B_ * N_)          // 25088 rows
#define KF_TOT (ENC_ / 16)       // 128 k16 fragments
#define FNP_TOT (ATT_ / 16)      // 32 fn-pairs

// gemm: block 128m x 128n x 64k; A via direct LDG, B smem 3-stage
#define NKS        32            // k-steps of 64
#define STAGE_U32  4096          // B stage: 8 fnp x 4 kf x 128 u32 = 16KB
#define SMEM_BYTES (3 * STAGE_U32 * 4)   // 49152

// ---- scratch (__device__ globals: sanctioned no-alloc workaround) ----
__device__ float    g_att2[B_ * ATT_];
__device__ float    g_epart[M_ * 4];
__device__ uint32_t g_Bf2[FNP_TOT * KF_TOT * 128];  // B fp16 pair-frag, permuted k

// ============================================================
// helpers
// ============================================================
__device__ __forceinline__ uint32_t pack_h2(__half lo, __half hi) {
    __half2 p; p.x = lo; p.y = hi;
    return *reinterpret_cast<uint32_t*>(&p);
}
__device__ __forceinline__ uint32_t cvt2h(float hi, float lo) {
    uint32_t r;
    asm("cvt.rn.f16x2.f32 %0, %1, %2;" : "=r"(r) : "f"(hi), "f"(lo));
    return r;
}
__device__ __forceinline__ void cp16(uint32_t saddr, const void* g) {
    asm volatile("cp.async.cg.shared.global [%0], [%1], 16;\n" :: "r"(saddr), "l"(g));
}
__device__ __forceinline__ void cp_commit() { asm volatile("cp.async.commit_group;\n"); }
template <int NN> __device__ __forceinline__ void cp_wait() {
    asm volatile("cp.async.wait_group %0;\n" :: "n"(NN));
}
__device__ __forceinline__ void mma16816(float c[4], const uint32_t a[4], const uint32_t b[2]) {
    asm volatile(
        "mma.sync.aligned.m16n8k16.row.col.f32.f16.f16.f32 "
        "{%0,%1,%2,%3}, {%4,%5,%6,%7}, {%8,%9}, {%0,%1,%2,%3};\n"
        : "+f"(c[0]), "+f"(c[1]), "+f"(c[2]), "+f"(c[3])
        : "r"(a[0]), "r"(a[1]), "r"(a[2]), "r"(a[3]),
          "r"(b[0]), "r"(b[1]));
}

// ============================================================
// Kernel 1: att2 = decoder_hidden @ W_dec + b_dec   (fp32 exact)
// ============================================================
__global__ void att2_kernel(const float* __restrict__ dec,
                            const float* __restrict__ Wdec,
                            const float* __restrict__ bdec) {
    __shared__ float ds[DEC_];
    int b = blockIdx.x, a = threadIdx.x;
    ds[a] = dec[b * DEC_ + a];
    __syncthreads();
    float acc = bdec[a];
#pragma unroll 8
    for (int d = 0; d < DEC_; d++) acc += ds[d] * Wdec[d * ATT_ + a];
    g_att2[b * ATT_ + a] = acc;
}

// ============================================================
// Prepack B: W_enc [K][N] -> fp16 PAIRED frag layout, permuted k
//   layout [fnp][kf][lane][rr4]; rr: fn_sub = rr>>1, kreg = rr&1
//   n = fnp*16 + fn_sub*8 + (lane>>2)
//   k = kf*16 + (lane&3)*4 + kreg*2   (permuted; A uses same relabeling)
// ============================================================
__global__ void prepackB(const float* __restrict__ Wenc) {
    int idx = blockIdx.x * 256 + threadIdx.x;
    int rr   = idx & 3;
    int lane = (idx >> 2) & 31;
    int kf   = (idx >> 7) & (KF_TOT - 1);
    int fnp  = idx >> 14;
    int n = fnp * 16 + (rr >> 1) * 8 + (lane >> 2);
    int k = kf * 16 + (lane & 3) * 4 + (rr & 1) * 2;
    float v0 = Wenc[(size_t)k * ATT_ + n];
    float v1 = Wenc[(size_t)(k + 1) * ATT_ + n];
    g_Bf2[idx] = pack_h2(__float2half_rn(v0), __float2half_rn(v1));
}

// ============================================================
// Kernel 2: HMMA GEMM — A direct from GMEM (LDG.128 + cvt), B smem
//   block 128m x 128n x 64k; 8 warps (4M x 2N), warp tile 32x64
//   grid (nchunk=4 fastest, mtile=196) for L2 reuse of A
// ============================================================
__global__ __launch_bounds__(256, 2)
void gemm_e_kernel(const float* __restrict__ enc,
                   const float* __restrict__ benc,
                   const float* __restrict__ Wfull) {
    extern __shared__ uint32_t sm[];   // 3 B-stages x 4096 u32
    const int tid = threadIdx.x;
    const int lane = tid & 31, wid = tid >> 5;
    const int warpM = wid & 3, warpN = wid >> 2;   // 4M x 2N
    const int nchunk = blockIdx.x;     // 0..3
    const int mtile  = blockIdx.y;     // 0..195
    const int m0g = mtile * 128;
    const int g = lane >> 2, tig = lane & 3;

    const uint32_t smbase = (uint32_t)__cvta_generic_to_shared(sm);

    float acc[2][8][4];
#pragma unroll
    for (int i = 0; i < 2; i++)
#pragma unroll
        for (int j = 0; j < 8; j++)
#pragma unroll
            for (int q = 0; q < 4; q++) acc[i][j][q] = 0.f;

    // ---- B stage loader: 1024 x 16B chunks, 4/thread ----
    auto issue = [&](int ks, int st) {
        const uint32_t so = smbase + (uint32_t)(st * STAGE_U32) * 4u;
#pragma unroll
        for (int i = 0; i < 4; i++) {
            int c = i * 256 + tid;           // 0..1023
            int fnp = c >> 7, kf = (c >> 5) & 3, ln = c & 31;
            const void* src = g_Bf2 +
                ((size_t)(nchunk * 8 + fnp) * KF_TOT + (ks * 4 + kf)) * 128 + ln * 4;
            uint32_t dst = so + (uint32_t)((fnp * 4 + kf) * 128 + ln * 4) * 4u;
            cp16(dst, src);
        }
        cp_commit();
    };

    issue(0, 0);
    issue(1, 1);

    // ---- A row pointer: 4 rows per thread at fixed strides ----
    const float* pA = enc + (size_t)(m0g + warpM * 32 + g) * ENC_ + tig * 4;
    // row offsets (floats): +8 rows, +16 rows, +24 rows
    const size_t R8 = (size_t)8 * ENC_, R16 = (size_t)16 * ENC_, R24 = (size_t)24 * ENC_;

    // preload step 0
    float4 cur[4];
    cur[0] = *reinterpret_cast<const float4*>(pA);
    cur[1] = *reinterpret_cast<const float4*>(pA + R8);
    cur[2] = *reinterpret_cast<const float4*>(pA + R16);
    cur[3] = *reinterpret_cast<const float4*>(pA + R24);

    for (int s = 0; s < NKS; s++) {
        const int st = s % 3;
        if (s + 1 < NKS) cp_wait<1>(); else cp_wait<0>();
        __syncthreads();
        if (s + 2 < NKS) issue(s + 2, (s + 2) % 3);

        const int sb = st * STAGE_U32;
        const float* pI = pA + (size_t)s * 64;
#pragma unroll
        for (int kf = 0; kf < 4; kf++) {
            // prefetch next step's A (except very last step)
            float4 nxt[4];
            const bool doPref = (kf < 3) || (s + 1 < NKS);
            if (doPref) {
                const float* pN = pI + (kf + 1) * 16;
                nxt[0] = *reinterpret_cast<const float4*>(pN);
                nxt[1] = *reinterpret_cast<const float4*>(pN + R8);
                nxt[2] = *reinterpret_cast<const float4*>(pN + R16);
                nxt[3] = *reinterpret_cast<const float4*>(pN + R24);
            }
            // A fragments from cur
            uint32_t a[2][4];
            a[0][0] = cvt2h(cur[0].y, cur[0].x);
            a[0][1] = cvt2h(cur[1].y, cur[1].x);
            a[0][2] = cvt2h(cur[0].w, cur[0].z);
            a[0][3] = cvt2h(cur[1].w, cur[1].z);
            a[1][0] = cvt2h(cur[2].y, cur[2].x);
            a[1][1] = cvt2h(cur[3].y, cur[3].x);
            a[1][2] = cvt2h(cur[2].w, cur[2].z);
            a[1][3] = cvt2h(cur[3].w, cur[3].z);
            // B fragments: 4x LDS.128 (paired fn)
            uint32_t b[8][2];
#pragma unroll
            for (int fnp = 0; fnp < 4; fnp++) {
                int fnpAbs = warpN * 4 + fnp;
                uint4 v = *reinterpret_cast<const uint4*>(
                    &sm[sb + (fnpAbs * 4 + kf) * 128 + lane * 4]);
                b[fnp * 2][0] = v.x;  b[fnp * 2][1] = v.y;
                b[fnp * 2 + 1][0] = v.z;  b[fnp * 2 + 1][1] = v.w;
            }
#pragma unroll
            for (int fm = 0; fm < 2; fm++)
#pragma unroll
                for (int fn = 0; fn < 8; fn++)
                    mma16816(acc[fm][fn], a[fm], b[fn]);
            if (doPref) {
                cur[0] = nxt[0]; cur[1] = nxt[1];
                cur[2] = nxt[2]; cur[3] = nxt[3];
            }
        }
    }

    // ---- fused epilogue: v = relu(acc + b_enc + att2); e += v * W_full ----
    float ep[2][2] = {{0.f, 0.f}, {0.f, 0.f}};
#pragma unroll
    for (int fm = 0; fm < 2; fm++) {
        int r0 = warpM * 32 + fm * 16 + g;
        int b0 = (m0g + r0) / N_;
        int b1 = (m0g + r0 + 8) / N_;
#pragma unroll
        for (int fn = 0; fn < 8; fn++) {
            int a0i = nchunk * 128 + warpN * 64 + fn * 8 + tig * 2;
            int a1i = a0i + 1;
            float w0 = Wfull[a0i], w1 = Wfull[a1i];
            float be0 = benc[a0i], be1 = benc[a1i];
            float t00 = g_att2[b0 * ATT_ + a0i];
            float t01 = g_att2[b0 * ATT_ + a1i];
            float t10 = g_att2[b1 * ATT_ + a0i];
            float t11 = g_att2[b1 * ATT_ + a1i];
            ep[fm][0] += fmaxf(acc[fm][fn][0] + be0 + t00, 0.f) * w0;
            ep[fm][0] += fmaxf(acc[fm][fn][1] + be1 + t01, 0.f) * w1;
            ep[fm][1] += fmaxf(acc[fm][fn][2] + be0 + t10, 0.f) * w0;
            ep[fm][1] += fmaxf(acc[fm][fn][3] + be1 + t11, 0.f) * w1;
        }
    }
#pragma unroll
    for (int off = 1; off <= 2; off <<= 1)
#pragma unroll
        for (int fm = 0; fm < 2; fm++) {
            ep[fm][0] += __shfl_xor_sync(0xffffffffu, ep[fm][0], off);
            ep[fm][1] += __shfl_xor_sync(0xffffffffu, ep[fm][1], off);
        }

    __syncthreads();
    float* e_red = reinterpret_cast<float*>(sm);  // [128][2]
    if (tig == 0) {
#pragma unroll
        for (int fm = 0; fm < 2; fm++) {
            int r0 = warpM * 32 + fm * 16 + g;
            e_red[r0 * 2 + warpN]       = ep[fm][0];
            e_red[(r0 + 8) * 2 + warpN] = ep[fm][1];
        }
    }
    __syncthreads();
    if (tid < 128)
        g_epart[(size_t)(m0g + tid) * 4 + nchunk] = e_red[tid * 2] + e_red[tid * 2 + 1];
}

// ============================================================
// Kernel 3: fused softmax + awe
//   grid (2, B): each block recomputes softmax for its b (cheap),
//   block x==0 writes alpha; both halves do the weighted encoding.
// ============================================================
__global__ void awe_kernel(const float* __restrict__ enc,
                           const float* __restrict__ bfull_p,
                           float* __restrict__ out_alpha,
                           float* __restrict__ out_awe) {
    __shared__ float al[N_];
    __shared__ float red[256];
    int b = blockIdx.y, tid = threadIdx.x;
    float bfull = *bfull_p;

    // ---- softmax over n (196) ----
    float ev = -INFINITY;
    float sval = 0.f;
    if (tid < N_) {
        const float* p = &g_epart[(size_t)(b * N_ + tid) * 4];
        sval = bfull + p[0] + p[1] + p[2] + p[3];
        ev = sval;
    }
    red[tid] = ev; __syncthreads();
#pragma unroll
    for (int off = 128; off > 0; off >>= 1) {
        if (tid < off) red[tid] = fmaxf(red[tid], red[tid + off]);
        __syncthreads();
    }
    float mx = red[0]; __syncthreads();
    float ex = 0.f;
    if (tid < N_) ex = expf(sval - mx);
    red[tid] = ex; __syncthreads();
#pragma unroll
    for (int off = 128; off > 0; off >>= 1) {
        if (tid < off) red[tid] += red[tid + off];
        __syncthreads();
    }
    float inv = 1.f / red[0];
    if (tid < N_) {
        float a = ex * inv;
        al[tid] = a;
        if (blockIdx.x == 0) out_alpha[b * N_ + tid] = a;
    }
    __syncthreads();

    // ---- weighted encoding: float4 + dual accumulator ----
    int e0 = (blockIdx.x * 256 + tid) * 4;
    const float4* p = reinterpret_cast<const float4*>(enc + (size_t)b * N_ * ENC_ + e0);
    float4 acc0 = make_float4(0.f, 0.f, 0.f, 0.f);
    float4 acc1 = make_float4(0.f, 0.f, 0.f, 0.f);
#pragma unroll 7
    for (int n = 0; n < 98; n++) {
        float4 v0 = p[(size_t)n * (ENC_ / 4)];
        float4 v1 = p[(size_t)(n + 98) * (ENC_ / 4)];
        float a0 = al[n], a1 = al[n + 98];
        acc0.x += a0 * v0.x; acc0.y += a0 * v0.y;
        acc0.z += a0 * v0.z; acc0.w += a0 * v0.w;
        acc1.x += a1 * v1.x; acc1.y += a1 * v1.y;
        acc1.z += a1 * v1.z; acc1.w += a1 * v1.w;
    }
    float4 r;
    r.x = acc0.x + acc1.x; r.y = acc0.y + acc1.y;
    r.z = acc0.z + acc1.z; r.w = acc0.w + acc1.w;
    *reinterpret_cast<float4*>(out_awe + (size_t)b * ENC_ + e0) = r;
}

// ============================================================
extern "C" void kernel_launch(void* const* d_in, const int* in_sizes, int n_in,
                              void* d_out, int out_size) {
    const float* enc   = (const float*)d_in[0];
    const float* dech  = (const float*)d_in[1];
    const float* Wenc  = (const float*)d_in[2];
    const float* benc  = (const float*)d_in[3];
    const float* Wdec  = (const float*)d_in[4];
    const float* bdec  = (const float*)d_in[5];
    const float* Wfull = (const float*)d_in[6];
    const float* bfull = (const float*)d_in[7];

    float* out       = (float*)d_out;
    float* out_awe   = out;
    float* out_alpha = out + (size_t)B_ * ENC_;

    cudaFuncSetAttribute(gemm_e_kernel,
                         cudaFuncAttributeMaxDynamicSharedMemorySize, SMEM_BYTES);

    att2_kernel<<<B_, ATT_>>>(dech, Wdec, bdec);
    prepackB<<<FNP_TOT * KF_TOT * 128 / 256, 256>>>(Wenc);

    dim3 g2(4, 196);                           // nchunk fastest -> A L2 reuse
    gemm_e_kernel<<<g2, 256, SMEM_BYTES>>>(enc, benc, Wfull);

    dim3 g3(2, B_);
    awe_kernel<<<g3, 256>>>(enc, bfull, out_alpha, out_awe);
}

// round 10
// speedup vs baseline: 1.0127x; 1.0127x over previous
#include <cuda_runtime.h>
#include <cuda_fp16.h>
#include <stdint.h>
#include <math.h>

#define B_    128
#define N_    196
#define ENC_  2048
#define DEC_  512
#define ATT_  512
#define M_    (B_ * N_)          // 25088 rows
#define KF_TOT (ENC_ / 16)       // 128 k16 fragments
#define FNP_TOT (ATT_ / 16)      // 32 fn-pairs

// gemm: block 128m x 128n x 64k; A fp16 smem (producer-convert), B cp.async
#define NKS        32            // k-steps of 64
#define A_ST_U32   4096          // A stage: 8 fm x 4 kf x 32 lane x 4 = 16KB
#define B_ST_U32   4096          // B stage: 8 fnp x 4 kf x 128 = 16KB
#define B_OFF      (3 * A_ST_U32)             // B stages after 3 A stages
#define SMEM_BYTES ((3 * A_ST_U32 + 3 * B_ST_U32) * 4)   // 98304

// ---- scratch (__device__ globals: sanctioned no-alloc workaround) ----
__device__ float    g_att2[B_ * ATT_];
__device__ float    g_epart[M_ * 4];
__device__ uint32_t g_Bf2[FNP_TOT * KF_TOT * 128];  // B fp16 pair-frag, permuted k

// ============================================================
// helpers
// ============================================================
__device__ __forceinline__ uint32_t pack_h2(__half lo, __half hi) {
    __half2 p; p.x = lo; p.y = hi;
    return *reinterpret_cast<uint32_t*>(&p);
}
__device__ __forceinline__ uint32_t cvt2h(float hi, float lo) {
    uint32_t r;
    asm("cvt.rn.f16x2.f32 %0, %1, %2;" : "=r"(r) : "f"(hi), "f"(lo));
    return r;
}
__device__ __forceinline__ void cp16(uint32_t saddr, const void* g) {
    asm volatile("cp.async.cg.shared.global [%0], [%1], 16;\n" :: "r"(saddr), "l"(g));
}
__device__ __forceinline__ void cp_commit() { asm volatile("cp.async.commit_group;\n"); }
template <int NN> __device__ __forceinline__ void cp_wait() {
    asm volatile("cp.async.wait_group %0;\n" :: "n"(NN));
}
__device__ __forceinline__ void sts128(uint32_t saddr, uint32_t r0, uint32_t r1,
                                       uint32_t r2, uint32_t r3) {
    asm volatile("st.shared.v4.b32 [%0], {%1, %2, %3, %4};\n"
                 :: "r"(saddr), "r"(r0), "r"(r1), "r"(r2), "r"(r3));
}
__device__ __forceinline__ void mma16816(float c[4], const uint32_t a[4], const uint32_t b[2]) {
    asm volatile(
        "mma.sync.aligned.m16n8k16.row.col.f32.f16.f16.f32 "
        "{%0,%1,%2,%3}, {%4,%5,%6,%7}, {%8,%9}, {%0,%1,%2,%3};\n"
        : "+f"(c[0]), "+f"(c[1]), "+f"(c[2]), "+f"(c[3])
        : "r"(a[0]), "r"(a[1]), "r"(a[2]), "r"(a[3]),
          "r"(b[0]), "r"(b[1]));
}

// ============================================================
// Kernel 1: att2 = decoder_hidden @ W_dec + b_dec   (fp32 exact)
// ============================================================
__global__ void att2_kernel(const float* __restrict__ dec,
                            const float* __restrict__ Wdec,
                            const float* __restrict__ bdec) {
    __shared__ float ds[DEC_];
    int b = blockIdx.x, a = threadIdx.x;
    ds[a] = dec[b * DEC_ + a];
    __syncthreads();
    float acc = bdec[a];
#pragma unroll 8
    for (int d = 0; d < DEC_; d++) acc += ds[d] * Wdec[d * ATT_ + a];
    g_att2[b * ATT_ + a] = acc;
}

// ============================================================
// Prepack B: W_enc [K][N] -> fp16 PAIRED frag layout, permuted k
//   layout [fnp][kf][lane][rr4]; rr = fn_sub*2 + kreg
//   n = fnp*16 + fn_sub*8 + (lane>>2)
//   k = kf*16 + (lane&3)*4 + kreg*2   (A uses same permutation)
// ============================================================
__global__ void prepackB(const float* __restrict__ Wenc) {
    int idx = blockIdx.x * 256 + threadIdx.x;
    int rr   = idx & 3;
    int lane = (idx >> 2) & 31;
    int kf   = (idx >> 7) & (KF_TOT - 1);
    int fnp  = idx >> 14;
    int n = fnp * 16 + (rr >> 1) * 8 + (lane >> 2);
    int k = kf * 16 + (lane & 3) * 4 + (rr & 1) * 2;
    float v0 = Wenc[(size_t)k * ATT_ + n];
    float v1 = Wenc[(size_t)(k + 1) * ATT_ + n];
    g_Bf2[idx] = pack_h2(__float2half_rn(v0), __float2half_rn(v1));
}

// ============================================================
// Kernel 2: HMMA GEMM — A fp16 smem via producer LDG+cvt+STS.128,
//   B via cp.async; block 128m x 128n x 64k; 8 warps (4M x 2N)
//   grid (nchunk=4 fastest, mtile=196) for L2 reuse of A
// ============================================================
__global__ __launch_bounds__(256, 2)
void gemm_e_kernel(const float* __restrict__ enc,
                   const float* __restrict__ benc,
                   const float* __restrict__ Wfull) {
    extern __shared__ uint32_t sm[];
    const int tid = threadIdx.x;
    const int lane = tid & 31, wid = tid >> 5;
    const int warpM = wid & 3, warpN = wid >> 2;   // 4M x 2N
    const int nchunk = blockIdx.x;     // 0..3
    const int mtile  = blockIdx.y;     // 0..195
    const int m0g = mtile * 128;
    const int g = lane >> 2, tig = lane & 3;

    const uint32_t smbase = (uint32_t)__cvta_generic_to_shared(sm);

    float acc[2][8][4];
#pragma unroll
    for (int i = 0; i < 2; i++)
#pragma unroll
        for (int j = 0; j < 8; j++)
#pragma unroll
            for (int q = 0; q < 4; q++) acc[i][j][q] = 0.f;

    // ---- producer pair decode: pair pi covers chunk c = pi*256+tid ----
    //   c -> fm(3b) kf(2b) ln(5b); rows fm*16+g', fm*16+8+g'; k = kf*16+tg*4
    // per-thread precomputed bases
    int pc0 = tid;                 // pair 0 chunk; pairs 1..3 add 256
    // A source base for this thread's pair-chunks is recomputed per pair.

    auto ldA = [&](int pi, int ks, float4& f0, float4& f1) {
        int c = pi * 256 + pc0;
        int fm = c >> 7, kf = (c >> 5) & 3, ln = c & 31;
        const float* src = enc + (size_t)(m0g + fm * 16 + (ln >> 2)) * ENC_
                         + ks * 64 + kf * 16 + (ln & 3) * 4;
        f0 = *reinterpret_cast<const float4*>(src);
        f1 = *reinterpret_cast<const float4*>(src + 8 * ENC_);
    };
    auto stA = [&](int pi, int sa, const float4& f0, const float4& f1) {
        int c = pi * 256 + pc0;
        int fm = c >> 7, kf = (c >> 5) & 3, ln = c & 31;
        uint32_t addr = smbase + (uint32_t)(sa * A_ST_U32 + (fm * 4 + kf) * 128 + ln * 4) * 4u;
        sts128(addr, cvt2h(f0.y, f0.x), cvt2h(f1.y, f1.x),
                     cvt2h(f0.w, f0.z), cvt2h(f1.w, f1.z));
    };

    // ---- B stage loader: 1024 x 16B chunks, 4/thread ----
    auto issueB = [&](int ks, int st) {
        const uint32_t so = smbase + (uint32_t)(B_OFF + st * B_ST_U32) * 4u;
#pragma unroll
        for (int i = 0; i < 4; i++) {
            int c = i * 256 + tid;
            int fnp = c >> 7, kf = (c >> 5) & 3, ln = c & 31;
            const void* src = g_Bf2 +
                ((size_t)(nchunk * 8 + fnp) * KF_TOT + (ks * 4 + kf)) * 128 + ln * 4;
            uint32_t dst = so + (uint32_t)((fnp * 4 + kf) * 128 + ln * 4) * 4u;
            cp16(dst, src);
        }
        cp_commit();
    };

    // ---- prime: A stages 0,1 + B stages 0,1 ----
    {
        float4 f0, f1;
#pragma unroll
        for (int pi = 0; pi < 4; pi++) { ldA(pi, 0, f0, f1); stA(pi, 0, f0, f1); }
#pragma unroll
        for (int pi = 0; pi < 4; pi++) { ldA(pi, 1, f0, f1); stA(pi, 1, f0, f1); }
    }
    issueB(0, 0);
    issueB(1, 1);

    for (int s = 0; s < NKS; s++) {
        const int st = s % 3;
        if (s + 1 < NKS) cp_wait<1>(); else cp_wait<0>();
        __syncthreads();

        const bool pref = (s + 2 < NKS);
        const int sa = st * A_ST_U32;              // A stage for this step
        const int sb = B_OFF + st * B_ST_U32;      // B stage for this step
        const int sp = ((s + 2) % 3);              // produce target stage

        float4 p0a, p0b, p1a, p1b;
        if (pref) { ldA(0, s + 2, p0a, p0b); ldA(1, s + 2, p1a, p1b); }

        // compute one kf: LDS A (direct frags) + LDS B + 16 mma
        auto domma = [&](int kf) {
            uint32_t a[2][4];
#pragma unroll
            for (int fm = 0; fm < 2; fm++) {
                int fmAbs = warpM * 2 + fm;
                uint4 v = *reinterpret_cast<const uint4*>(
                    &sm[sa + (fmAbs * 4 + kf) * 128 + lane * 4]);
                a[fm][0] = v.x; a[fm][1] = v.y; a[fm][2] = v.z; a[fm][3] = v.w;
            }
            uint32_t b[8][2];
#pragma unroll
            for (int fnp = 0; fnp < 4; fnp++) {
                int fnpAbs = warpN * 4 + fnp;
                uint4 v = *reinterpret_cast<const uint4*>(
                    &sm[sb + (fnpAbs * 4 + kf) * 128 + lane * 4]);
                b[fnp * 2][0] = v.x;      b[fnp * 2][1] = v.y;
                b[fnp * 2 + 1][0] = v.z;  b[fnp * 2 + 1][1] = v.w;
            }
#pragma unroll
            for (int fm = 0; fm < 2; fm++)
#pragma unroll
                for (int fn = 0; fn < 8; fn++)
                    mma16816(acc[fm][fn], a[fm], b[fn]);
        };

        domma(0);
        if (pref) { stA(0, sp, p0a, p0b); stA(1, sp, p1a, p1b); }
        if (pref) { ldA(2, s + 2, p0a, p0b); ldA(3, s + 2, p1a, p1b); }
        domma(1);
        if (pref) { stA(2, sp, p0a, p0b); stA(3, sp, p1a, p1b); }
        if (pref) issueB(s + 2, sp);
        domma(2);
        domma(3);
    }

    // ---- fused epilogue: v = relu(acc + b_enc + att2); e += v * W_full ----
    float ep[2][2] = {{0.f, 0.f}, {0.f, 0.f}};
#pragma unroll
    for (int fm = 0; fm < 2; fm++) {
        int r0 = warpM * 32 + fm * 16 + g;
        int b0 = (m0g + r0) / N_;
        int b1 = (m0g + r0 + 8) / N_;
#pragma unroll
        for (int fn = 0; fn < 8; fn++) {
            int a0i = nchunk * 128 + warpN * 64 + fn * 8 + tig * 2;
            int a1i = a0i + 1;
            float w0 = Wfull[a0i], w1 = Wfull[a1i];
            float be0 = benc[a0i], be1 = benc[a1i];
            float t00 = g_att2[b0 * ATT_ + a0i];
            float t01 = g_att2[b0 * ATT_ + a1i];
            float t10 = g_att2[b1 * ATT_ + a0i];
            float t11 = g_att2[b1 * ATT_ + a1i];
            ep[fm][0] += fmaxf(acc[fm][fn][0] + be0 + t00, 0.f) * w0;
            ep[fm][0] += fmaxf(acc[fm][fn][1] + be1 + t01, 0.f) * w1;
            ep[fm][1] += fmaxf(acc[fm][fn][2] + be0 + t10, 0.f) * w0;
            ep[fm][1] += fmaxf(acc[fm][fn][3] + be1 + t11, 0.f) * w1;
        }
    }
#pragma unroll
    for (int off = 1; off <= 2; off <<= 1)
#pragma unroll
        for (int fm = 0; fm < 2; fm++) {
            ep[fm][0] += __shfl_xor_sync(0xffffffffu, ep[fm][0], off);
            ep[fm][1] += __shfl_xor_sync(0xffffffffu, ep[fm][1], off);
        }

    __syncthreads();
    float* e_red = reinterpret_cast<float*>(sm);  // [128][2]
    if (tig == 0) {
#pragma unroll
        for (int fm = 0; fm < 2; fm++) {
            int r0 = warpM * 32 + fm * 16 + g;
            e_red[r0 * 2 + warpN]       = ep[fm][0];
            e_red[(r0 + 8) * 2 + warpN] = ep[fm][1];
        }
    }
    __syncthreads();
    if (tid < 128)
        g_epart[(size_t)(m0g + tid) * 4 + nchunk] = e_red[tid * 2] + e_red[tid * 2 + 1];
}

// ============================================================
// Kernel 3: fused softmax + awe
//   grid (2, B): each block recomputes softmax for its b,
//   block x==0 writes alpha; 4-way n-split accumulators (MLP 8 loads)
// ============================================================
__global__ void awe_kernel(const float* __restrict__ enc,
                           const float* __restrict__ bfull_p,
                           float* __restrict__ out_alpha,
                           float* __restrict__ out_awe) {
    __shared__ float al[N_];
    __shared__ float red[256];
    int b = blockIdx.y, tid = threadIdx.x;
    float bfull = *bfull_p;

    // ---- softmax over n (196) ----
    float ev = -INFINITY;
    float sval = 0.f;
    if (tid < N_) {
        const float* p = &g_epart[(size_t)(b * N_ + tid) * 4];
        sval = bfull + p[0] + p[1] + p[2] + p[3];
        ev = sval;
    }
    red[tid] = ev; __syncthreads();
#pragma unroll
    for (int off = 128; off > 0; off >>= 1) {
        if (tid < off) red[tid] = fmaxf(red[tid], red[tid + off]);
        __syncthreads();
    }
    float mx = red[0]; __syncthreads();
    float ex = 0.f;
    if (tid < N_) ex = expf(sval - mx);
    red[tid] = ex; __syncthreads();
#pragma unroll
    for (int off = 128; off > 0; off >>= 1) {
        if (tid < off) red[tid] += red[tid + off];
        __syncthreads();
    }
    float inv = 1.f / red[0];
    if (tid < N_) {
        float a = ex * inv;
        al[tid] = a;
        if (blockIdx.x == 0) out_alpha[b * N_ + tid] = a;
    }
    __syncthreads();

    // ---- weighted encoding: float4, 4 accumulator chains (49*4=196) ----
    int e0 = (blockIdx.x * 256 + tid) * 4;
    const float4* p = reinterpret_cast<const float4*>(enc + (size_t)b * N_ * ENC_ + e0);
    float4 a0 = make_float4(0.f, 0.f, 0.f, 0.f);
    float4 a1 = make_float4(0.f, 0.f, 0.f, 0.f);
    float4 a2 = make_float4(0.f, 0.f, 0.f, 0.f);
    float4 a3 = make_float4(0.f, 0.f, 0.f, 0.f);
#pragma unroll 7
    for (int n = 0; n < 49; n++) {
        float4 v0 = p[(size_t)n * (ENC_ / 4)];
        float4 v1 = p[(size_t)(n + 49) * (ENC_ / 4)];
        float4 v2 = p[(size_t)(n + 98) * (ENC_ / 4)];
        float4 v3 = p[(size_t)(n + 147) * (ENC_ / 4)];
        float w0 = al[n], w1 = al[n + 49], w2 = al[n + 98], w3 = al[n + 147];
        a0.x += w0 * v0.x; a0.y += w0 * v0.y; a0.z += w0 * v0.z; a0.w += w0 * v0.w;
        a1.x += w1 * v1.x; a1.y += w1 * v1.y; a1.z += w1 * v1.z; a1.w += w1 * v1.w;
        a2.x += w2 * v2.x; a2.y += w2 * v2.y; a2.z += w2 * v2.z; a2.w += w2 * v2.w;
        a3.x += w3 * v3.x; a3.y += w3 * v3.y; a3.z += w3 * v3.z; a3.w += w3 * v3.w;
    }
    float4 r;
    r.x = (a0.x + a1.x) + (a2.x + a3.x);
    r.y = (a0.y + a1.y) + (a2.y + a3.y);
    r.z = (a0.z + a1.z) + (a2.z + a3.z);
    r.w = (a0.w + a1.w) + (a2.w + a3.w);
    *reinterpret_cast<float4*>(out_awe + (size_t)b * ENC_ + e0) = r;
}

// ============================================================
extern "C" void kernel_launch(void* const* d_in, const int* in_sizes, int n_in,
                              void* d_out, int out_size) {
    const float* enc   = (const float*)d_in[0];
    const float* dech  = (const float*)d_in[1];
    const float* Wenc  = (const float*)d_in[2];
    const float* benc  = (const float*)d_in[3];
    const float* Wdec  = (const float*)d_in[4];
    const float* bdec  = (const float*)d_in[5];
    const float* Wfull = (const float*)d_in[6];
    const float* bfull = (const float*)d_in[7];

    float* out       = (float*)d_out;
    float* out_awe   = out;
    float* out_alpha = out + (size_t)B_ * ENC_;

    cudaFuncSetAttribute(gemm_e_kernel,
                         cudaFuncAttributeMaxDynamicSharedMemorySize, SMEM_BYTES);

    att2_kernel<<<B_, ATT_>>>(dech, Wdec, bdec);
    prepackB<<<FNP_TOT * KF_TOT * 128 / 256, 256>>>(Wenc);

    dim3 g2(4, 196);                           // nchunk fastest -> A L2 reuse
    gemm_e_kernel<<<g2, 256, SMEM_BYTES>>>(enc, benc, Wfull);

    dim3 g3(2, B_);
    awe_kernel<<<g3, 256>>>(enc, bfull, out_alpha, out_awe);
}

// round 11
// speedup vs baseline: 1.1273x; 1.1132x over previous
#include <cuda_runtime.h>
#include <cuda_fp16.h>
#include <stdint.h>
#include <math.h>

#define B_    128
#define N_    196
#define ENC_  2048
#define DEC_  512
#define ATT_  512
#define M_    (B_ * N_)          // 25088 rows
#define KF_TOT (ENC_ / 16)       // 128 k16 fragments
#define FN_TOT (ATT_ / 8)        // 64  n8 fragments

// gemm tiling: block 128m x 128n x 64k, 2-stage, 2 CTAs/SM  (R8 dataflow)
// stage: A raw fp32 128x64 (32KB) + B fp16 frag-major (16KB) = 48KB
#define NKS        32            // k-steps of 64
#define STAGE_U32  12288         // 48KB per stage
#define SMEM_BYTES (2 * STAGE_U32 * 4)   // 98304

// ---- scratch (__device__ globals: sanctioned no-alloc workaround) ----
__device__ float    g_att2[B_ * ATT_];
__device__ float    g_epart[M_ * 4];
__device__ uint32_t g_Bf[FN_TOT * KF_TOT * 64];   // B fp16 frag-major, permuted k

// ============================================================
// helpers
// ============================================================
__device__ __forceinline__ uint32_t pack_h2(__half lo, __half hi) {
    __half2 p; p.x = lo; p.y = hi;       // .x = low 16 bits (lower k index)
    return *reinterpret_cast<uint32_t*>(&p);
}
__device__ __forceinline__ uint32_t cvt2h(float hi, float lo) {
    uint32_t r;
    asm("cvt.rn.f16x2.f32 %0, %1, %2;" : "=r"(r) : "f"(hi), "f"(lo));
    return r;
}
__device__ __forceinline__ void cp16(uint32_t saddr, const void* g) {
    asm volatile("cp.async.cg.shared.global [%0], [%1], 16;\n" :: "r"(saddr), "l"(g));
}
__device__ __forceinline__ void cp_commit() { asm volatile("cp.async.commit_group;\n"); }
template <int NN> __device__ __forceinline__ void cp_wait() {
    asm volatile("cp.async.wait_group %0;\n" :: "n"(NN));
}
__device__ __forceinline__ void mma16816(float c[4], const uint32_t a[4], const uint32_t b[2]) {
    asm volatile(
        "mma.sync.aligned.m16n8k16.row.col.f32.f16.f16.f32 "
        "{%0,%1,%2,%3}, {%4,%5,%6,%7}, {%8,%9}, {%0,%1,%2,%3};\n"
        : "+f"(c[0]), "+f"(c[1]), "+f"(c[2]), "+f"(c[3])
        : "r"(a[0]), "r"(a[1]), "r"(a[2]), "r"(a[3]),
          "r"(b[0]), "r"(b[1]));
}

// ============================================================
// Kernel 1: att2 = decoder_hidden @ W_dec + b_dec   (fp32 exact)
// ============================================================
__global__ void att2_kernel(const float* __restrict__ dec,
                            const float* __restrict__ Wdec,
                            const float* __restrict__ bdec) {
    __shared__ float ds[DEC_];
    int b = blockIdx.x, a = threadIdx.x;
    ds[a] = dec[b * DEC_ + a];
    __syncthreads();
    float acc = bdec[a];
#pragma unroll 8
    for (int d = 0; d < DEC_; d++) acc += ds[d] * Wdec[d * ATT_ + a];
    g_att2[b * ATT_ + a] = acc;
}

// ============================================================
// Prepack B: W_enc [K][N] -> fp16 frag-major with PERMUTED k layout
//   position (tig, kreg, elem) holds actual k = kf*16 + tig*4 + kreg*2 + elem
//   (A uses the same permutation -> mma result identical)
// ============================================================
__global__ void prepackB(const float* __restrict__ Wenc) {
    int idx = blockIdx.x * 256 + threadIdx.x;
    int reg  = idx & 1;                  // kreg
    int lane = (idx >> 1) & 31;
    int kf   = (idx >> 6) & (KF_TOT - 1);
    int fn   = idx >> 13;
    int n = fn * 8 + (lane >> 2);
    int k = kf * 16 + (lane & 3) * 4 + reg * 2;   // permuted
    float v0 = Wenc[(size_t)k * ATT_ + n];
    float v1 = Wenc[(size_t)(k + 1) * ATT_ + n];
    g_Bf[idx] = pack_h2(__float2half_rn(v0), __float2half_rn(v1));
}

// ============================================================
// Kernel 2: HMMA GEMM (1-term fp16, A converted in-kernel) + epilogue
//   block 128m x 128n x 64k; 8 warps (4M x 2N), warp tile 32x64
//   A: raw fp32 rows, additive-swizzled; cvt.rn.f16x2.f32 in regs
//   grid (nchunk=4 fastest, mtile=196) for L2 reuse of A
//   == exact R8 dataflow (measured 160us) ==
// ============================================================
__global__ __launch_bounds__(256, 2)
void gemm_e_kernel(const float* __restrict__ enc,
                   const float* __restrict__ benc,
                   const float* __restrict__ Wfull) {
    extern __shared__ uint32_t sm[];   // 2 stages x 12288 u32
    const int tid = threadIdx.x;
    const int lane = tid & 31, wid = tid >> 5;
    const int warpM = wid & 3, warpN = wid >> 2;   // 4M x 2N
    const int nchunk = blockIdx.x;     // 0..3
    const int mtile  = blockIdx.y;     // 0..195
    const int m0g = mtile * 128;
    const int g = lane >> 2, tig = lane & 3;

    const uint32_t smbase = (uint32_t)__cvta_generic_to_shared(sm);

    float acc[2][8][4];
#pragma unroll
    for (int i = 0; i < 2; i++)
#pragma unroll
        for (int j = 0; j < 8; j++)
#pragma unroll
            for (int q = 0; q < 4; q++) acc[i][j][q] = 0.f;

    // ---- async load of k-step ks (64 k): A raw fp32 + B fp16; 12/thread ----
    auto issue = [&](int ks, int st) {
        const uint32_t so = smbase + (uint32_t)(st * STAGE_U32) * 4u;
#pragma unroll
        for (int i = 0; i < 12; i++) {
            int c = i * 256 + tid;           // 0..3071
            uint32_t dst;
            const void* src;
            if (c < 2048) {                  // A: row(128) x chunk16(16B=4 fp32)
                int row = c >> 4, cc = c & 15;
                int csw = (cc + row * 4) & 15;
                src = enc + (size_t)(m0g + row) * ENC_ + ks * 64 + cc * 4;
                dst = so + (uint32_t)(row * 64 + csw * 4) * 4u;
            } else {                         // B: fn16 kf4 q16
                int d = c - 2048;
                int fn = d >> 6, kf = (d >> 4) & 3, q = d & 15;
                src = g_Bf + ((size_t)(nchunk * 16 + fn) * KF_TOT + (ks * 4 + kf)) * 64 + q * 4;
                dst = so + (uint32_t)(8192 + (fn * 4 + kf) * 64 + q * 4) * 4u;
            }
            cp16(dst, src);
        }
        cp_commit();
    };

    issue(0, 0);

    for (int s = 0; s < NKS; s++) {
        const int st = s & 1;
        cp_wait<0>();                 // only group s outstanding here
        __syncthreads();              // all warps done reading buffer s-1
        if (s + 1 < NKS) issue(s + 1, st ^ 1);

        const int sb = st * STAGE_U32;
#pragma unroll
        for (int kf = 0; kf < 4; kf++) {
            // A fragments: 2x LDS.128 fp32 + 4 cvt per fm
            uint32_t a[2][4];
#pragma unroll
            for (int fm = 0; fm < 2; fm++) {
                int rbase = (warpM * 2 + fm) * 16;
                int r0 = rbase + g, r1 = rbase + 8 + g;
                int c0 = ((kf * 4 + tig) + r0 * 4) & 15;
                int c1 = ((kf * 4 + tig) + r1 * 4) & 15;
                float4 f0 = *reinterpret_cast<const float4*>(&sm[sb + r0 * 64 + c0 * 4]);
                float4 f1 = *reinterpret_cast<const float4*>(&sm[sb + r1 * 64 + c1 * 4]);
                a[fm][0] = cvt2h(f0.y, f0.x);
                a[fm][1] = cvt2h(f1.y, f1.x);
                a[fm][2] = cvt2h(f0.w, f0.z);
                a[fm][3] = cvt2h(f1.w, f1.z);
            }
            // B fragments: one LDS.64 per fn
            uint32_t b[8][2];
#pragma unroll
            for (int fn = 0; fn < 8; fn++) {
                int fnAbs = warpN * 8 + fn;
                uint2 v = *reinterpret_cast<const uint2*>(
                    &sm[sb + 8192 + (fnAbs * 4 + kf) * 64 + lane * 2]);
                b[fn][0] = v.x; b[fn][1] = v.y;
            }
#pragma unroll
            for (int fm = 0; fm < 2; fm++)
#pragma unroll
                for (int fn = 0; fn < 8; fn++)
                    mma16816(acc[fm][fn], a[fm], b[fn]);
        }
    }

    // ---- fused epilogue: v = relu(acc + b_enc + att2); e += v * W_full ----
    float ep[2][2] = {{0.f, 0.f}, {0.f, 0.f}};
#pragma unroll
    for (int fm = 0; fm < 2; fm++) {
        int r0 = warpM * 32 + fm * 16 + g;
        int b0 = (m0g + r0) / N_;
        int b1 = (m0g + r0 + 8) / N_;
#pragma unroll
        for (int fn = 0; fn < 8; fn++) {
            int a0i = nchunk * 128 + warpN * 64 + fn * 8 + tig * 2;
            int a1i = a0i + 1;
            float w0 = Wfull[a0i], w1 = Wfull[a1i];
            float be0 = benc[a0i], be1 = benc[a1i];
            float t00 = g_att2[b0 * ATT_ + a0i];
            float t01 = g_att2[b0 * ATT_ + a1i];
            float t10 = g_att2[b1 * ATT_ + a0i];
            float t11 = g_att2[b1 * ATT_ + a1i];
            ep[fm][0] += fmaxf(acc[fm][fn][0] + be0 + t00, 0.f) * w0;
            ep[fm][0] += fmaxf(acc[fm][fn][1] + be1 + t01, 0.f) * w1;
            ep[fm][1] += fmaxf(acc[fm][fn][2] + be0 + t10, 0.f) * w0;
            ep[fm][1] += fmaxf(acc[fm][fn][3] + be1 + t11, 0.f) * w1;
        }
    }
#pragma unroll
    for (int off = 1; off <= 2; off <<= 1)
#pragma unroll
        for (int fm = 0; fm < 2; fm++) {
            ep[fm][0] += __shfl_xor_sync(0xffffffffu, ep[fm][0], off);
            ep[fm][1] += __shfl_xor_sync(0xffffffffu, ep[fm][1], off);
        }

    __syncthreads();
    float* e_red = reinterpret_cast<float*>(sm);  // [128][2]
    if (tig == 0) {
#pragma unroll
        for (int fm = 0; fm < 2; fm++) {
            int r0 = warpM * 32 + fm * 16 + g;
            e_red[r0 * 2 + warpN]       = ep[fm][0];
            e_red[(r0 + 8) * 2 + warpN] = ep[fm][1];
        }
    }
    __syncthreads();
    if (tid < 128)
        g_epart[(size_t)(m0g + tid) * 4 + nchunk] = e_red[tid * 2] + e_red[tid * 2 + 1];
}

// ============================================================
// Kernel 3: fused softmax + awe
//   grid (2, B): each block recomputes softmax for its b,
//   block x==0 writes alpha; 7 accumulator chains (196 = 7*28)
// ============================================================
__global__ void awe_kernel(const float* __restrict__ enc,
                           const float* __restrict__ bfull_p,
                           float* __restrict__ out_alpha,
                           float* __restrict__ out_awe) {
    __shared__ float al[N_];
    __shared__ float red[256];
    int b = blockIdx.y, tid = threadIdx.x;
    float bfull = *bfull_p;

    // ---- softmax over n (196) ----
    float ev = -INFINITY;
    float sval = 0.f;
    if (tid < N_) {
        const float* p = &g_epart[(size_t)(b * N_ + tid) * 4];
        sval = bfull + p[0] + p[1] + p[2] + p[3];
        ev = sval;
    }
    red[tid] = ev; __syncthreads();
#pragma unroll
    for (int off = 128; off > 0; off >>= 1) {
        if (tid < off) red[tid] = fmaxf(red[tid], red[tid + off]);
        __syncthreads();
    }
    float mx = red[0]; __syncthreads();
    float ex = 0.f;
    if (tid < N_) ex = expf(sval - mx);
    red[tid] = ex; __syncthreads();
#pragma unroll
    for (int off = 128; off > 0; off >>= 1) {
        if (tid < off) red[tid] += red[tid + off];
        __syncthreads();
    }
    float inv = 1.f / red[0];
    if (tid < N_) {
        float a = ex * inv;
        al[tid] = a;
        if (blockIdx.x == 0) out_alpha[b * N_ + tid] = a;
    }
    __syncthreads();

    // ---- weighted encoding: float4, 7 accumulator chains (28*7=196) ----
    int e0 = (blockIdx.x * 256 + tid) * 4;
    const float4* p = reinterpret_cast<const float4*>(enc + (size_t)b * N_ * ENC_ + e0);
    float4 a0 = make_float4(0.f, 0.f, 0.f, 0.f);
    float4 a1 = make_float4(0.f, 0.f, 0.f, 0.f);
    float4 a2 = make_float4(0.f, 0.f, 0.f, 0.f);
    float4 a3 = make_float4(0.f, 0.f, 0.f, 0.f);
    float4 a4 = make_float4(0.f, 0.f, 0.f, 0.f);
    float4 a5 = make_float4(0.f, 0.f, 0.f, 0.f);
    float4 a6 = make_float4(0.f, 0.f, 0.f, 0.f);
#pragma unroll 4
    for (int n = 0; n < 28; n++) {
        float4 v0 = p[(size_t)n * (ENC_ / 4)];
        float4 v1 = p[(size_t)(n + 28) * (ENC_ / 4)];
        float4 v2 = p[(size_t)(n + 56) * (ENC_ / 4)];
        float4 v3 = p[(size_t)(n + 84) * (ENC_ / 4)];
        float4 v4 = p[(size_t)(n + 112) * (ENC_ / 4)];
        float4 v5 = p[(size_t)(n + 140) * (ENC_ / 4)];
        float4 v6 = p[(size_t)(n + 168) * (ENC_ / 4)];
        float w0 = al[n], w1 = al[n + 28], w2 = al[n + 56], w3 = al[n + 84];
        float w4 = al[n + 112], w5 = al[n + 140], w6 = al[n + 168];
        a0.x += w0 * v0.x; a0.y += w0 * v0.y; a0.z += w0 * v0.z; a0.w += w0 * v0.w;
        a1.x += w1 * v1.x; a1.y += w1 * v1.y; a1.z += w1 * v1.z; a1.w += w1 * v1.w;
        a2.x += w2 * v2.x; a2.y += w2 * v2.y; a2.z += w2 * v2.z; a2.w += w2 * v2.w;
        a3.x += w3 * v3.x; a3.y += w3 * v3.y; a3.z += w3 * v3.z; a3.w += w3 * v3.w;
        a4.x += w4 * v4.x; a4.y += w4 * v4.y; a4.z += w4 * v4.z; a4.w += w4 * v4.w;
        a5.x += w5 * v5.x; a5.y += w5 * v5.y; a5.z += w5 * v5.z; a5.w += w5 * v5.w;
        a6.x += w6 * v6.x; a6.y += w6 * v6.y; a6.z += w6 * v6.z; a6.w += w6 * v6.w;
    }
    float4 r;
    r.x = ((a0.x + a1.x) + (a2.x + a3.x)) + ((a4.x + a5.x) + a6.x);
    r.y = ((a0.y + a1.y) + (a2.y + a3.y)) + ((a4.y + a5.y) + a6.y);
    r.z = ((a0.z + a1.z) + (a2.z + a3.z)) + ((a4.z + a5.z) + a6.z);
    r.w = ((a0.w + a1.w) + (a2.w + a3.w)) + ((a4.w + a5.w) + a6.w);
    *reinterpret_cast<float4*>(out_awe + (size_t)b * ENC_ + e0) = r;
}

// ============================================================
extern "C" void kernel_launch(void* const* d_in, const int* in_sizes, int n_in,
                              void* d_out, int out_size) {
    const float* enc   = (const float*)d_in[0];
    const float* dech  = (const float*)d_in[1];
    const float* Wenc  = (const float*)d_in[2];
    const float* benc  = (const float*)d_in[3];
    const float* Wdec  = (const float*)d_in[4];
    const float* bdec  = (const float*)d_in[5];
    const float* Wfull = (const float*)d_in[6];
    const float* bfull = (const float*)d_in[7];

    float* out       = (float*)d_out;
    float* out_awe   = out;
    float* out_alpha = out + (size_t)B_ * ENC_;

    cudaFuncSetAttribute(gemm_e_kernel,
                         cudaFuncAttributeMaxDynamicSharedMemorySize, SMEM_BYTES);

    att2_kernel<<<B_, ATT_>>>(dech, Wdec, bdec);
    prepackB<<<FN_TOT * KF_TOT * 64 / 256, 256>>>(Wenc);

    dim3 g2(4, 196);                           // nchunk fastest -> A L2 reuse
    gemm_e_kernel<<<g2, 256, SMEM_BYTES>>>(enc, benc, Wfull);

    dim3 g3(2, B_);
    awe_kernel<<<g3, 256>>>(enc, bfull, out_alpha, out_awe);
}